// round 9
// baseline (speedup 1.0000x reference)
#include <cuda_runtime.h>

// PyramidDownSampling fused: out = [ x copy (2x256^3) | d1 3^3 s2 (2x128^3) | d2 5^3 s4 (2x64^3) ]
// R8: warp-per-dz layout (10 warps), forced 4 blocks/SM.
//   Lane holds X[4l..4l+3] (float4). Copy = direct STG.128. x-conv via 2
//   shfl_up; lane0 patched from uniform left-halo float2. Clamps are max(,0).

#define S  256
#define SS 65536
#define FULLM 0xffffffffu

__global__ __launch_bounds__(320, 4)
void pyramid_kernel(const float* __restrict__ x,
                    const float* __restrict__ k0,   // 27  (3x3x3)
                    const float* __restrict__ k1,   // 125 (5x5x5)
                    float* __restrict__ out)
{
    __shared__ float xr1s[100][64];   // x-reduced for d1, rows r = dz*10+dy
    __shared__ float xr2s[100][32];   // x-reduced for d2
    __shared__ float wsm[24];         // gz[0:3) gy[3:6) gx[6:9) hz[9:14) hy[14:19) hx[19:24)

    const int tid  = threadIdx.x;
    const int w    = tid >> 5;        // 0..9 == dz
    const int lane = tid & 31;

    // ---- exact 1D factors = axis marginals of the 3D kernels ----
    if (tid < 24) {
        float s = 0.f;
        if (tid < 9) {
            int axis = tid / 3, idx = tid % 3;
            for (int u = 0; u < 3; u++)
                for (int v = 0; v < 3; v++) {
                    int a, b, c;
                    if (axis == 0) { a = idx; b = u; c = v; }
                    else if (axis == 1) { a = u; b = idx; c = v; }
                    else { a = u; b = v; c = idx; }
                    s += k0[(a * 3 + b) * 3 + c];
                }
        } else {
            int q = tid - 9, axis = q / 5, idx = q % 5;
            for (int u = 0; u < 5; u++)
                for (int v = 0; v < 5; v++) {
                    int a, b, c;
                    if (axis == 0) { a = idx; b = u; c = v; }
                    else if (axis == 1) { a = u; b = idx; c = v; }
                    else { a = u; b = v; c = idx; }
                    s += k1[(a * 5 + b) * 5 + c];
                }
        }
        wsm[tid] = s;
    }
    __syncthreads();

    const int bxs = blockIdx.x * 128;
    const int y0  = blockIdx.y * 8;
    const int zc  = blockIdx.z & 31;
    const int n   = blockIdx.z >> 5;
    const int z0  = zc * 8;

    const float* xn   = x   + (size_t)n * S * SS;
    float*       outx = out + (size_t)n * S * SS;
    float*       out1 = out + (size_t)2 * S * SS + (size_t)n * 2097152;
    float*       out2 = out + (size_t)2 * S * SS + (size_t)2 * 2097152
                            + (size_t)n * 262144;

    const float gxw0 = wsm[6],  gxw1 = wsm[7],  gxw2 = wsm[8];
    const float hxw0 = wsm[19], hxw1 = wsm[20], hxw2 = wsm[21],
                hxw3 = wsm[22], hxw4 = wsm[23];

    const int  gx    = bxs + 4 * lane;           // lane holds X[gx..gx+3]
    const bool bx0   = (bxs == 0);
    const int  hloff = bx0 ? 0 : bxs - 2;        // uniform left-halo float2

    // ---- Phase A: warp w == dz plane, dy 0..9 unrolled ----
    {
        const int zs = z0 - 2 + w;               // <= 255 always
        const int gz = max(zs, 0);
        const float* zb = xn + ((size_t)gz << 16);
        float* ob = outx + ((size_t)zs << 16);   // valid only when w >= 2
        const bool zint = (w >= 2);

        #pragma unroll
        for (int dy = 0; dy < 10; dy++) {
            const int ys = y0 - 2 + dy;          // <= 255 always
            const int gy = max(ys, 0);
            const float* rp = zb + (gy << 8);

            const float4 v  = *(const float4*)(rp + gx);
            const float2 hl = *(const float2*)(rp + hloff);
            const float  e0 = hl.x;                       // X[bxs-2] (clamped)
            const float  e1 = bx0 ? hl.x : hl.y;          // X[bxs-1] (clamped)

            // identity copy straight from the load register
            if (zint && dy >= 2)
                __stcs((float4*)(ob + (ys << 8) + gx), v);

            // neighbor taps: X[4l-2], X[4l-1] = lane-1's v.z, v.w
            float p2 = __shfl_up_sync(FULLM, v.z, 1);
            float p3 = __shfl_up_sync(FULLM, v.w, 1);
            if (lane == 0) { p2 = e0; p3 = e1; }

            const int r = w * 10 + dy;
            // d1: xr1[2l] , xr1[2l+1]
            float2 o1;
            o1.x = gxw0 * p3  + gxw1 * v.x + gxw2 * v.y;
            o1.y = gxw0 * v.y + gxw1 * v.z + gxw2 * v.w;
            *(float2*)&xr1s[r][2 * lane] = o1;

            // d2: xr2[l] = h0*X[4l-2]+h1*X[4l-1]+h2*X[4l]+h3*X[4l+1]+h4*X[4l+2]
            xr2s[r][lane] = hxw0 * p2 + hxw1 * p3 + hxw2 * v.x
                          + hxw3 * v.y + hxw4 * v.z;
        }
    }
    __syncthreads();

    // ---- Phase B: d1 = 3x3 (z,y) taps -> 4i x 4j x 64l = 1024 outputs ----
    {
        const float gz0 = wsm[0], gz1 = wsm[1], gz2 = wsm[2];
        const float gy0 = wsm[3], gy1 = wsm[4], gy2 = wsm[5];
        for (int t = tid; t < 1024; t += 320) {
            const int l = t & 63;
            const int j = (t >> 6) & 3;
            const int i = t >> 8;
            const int rb = (2 * i + 1) * 10 + (2 * j + 1);
            float acc =
                gz0 * (gy0 * xr1s[rb     ][l] + gy1 * xr1s[rb +  1][l] + gy2 * xr1s[rb +  2][l])
              + gz1 * (gy0 * xr1s[rb + 10][l] + gy1 * xr1s[rb + 11][l] + gy2 * xr1s[rb + 12][l])
              + gz2 * (gy0 * xr1s[rb + 20][l] + gy1 * xr1s[rb + 21][l] + gy2 * xr1s[rb + 22][l]);
            const int od = (z0 >> 1) + i;
            const int oh = (y0 >> 1) + j;
            const int ow = (bxs >> 1) + l;
            __stcs(out1 + ((size_t)od * 128 + oh) * 128 + ow, acc);
        }
    }

    // ---- Phase B: d2 = 5x5 (z,y) taps -> 2i x 2j x 32l = 128 outputs ----
    if (tid < 128) {
        const float hz0 = wsm[9],  hz1 = wsm[10], hz2 = wsm[11],
                    hz3 = wsm[12], hz4 = wsm[13];
        const float hy0 = wsm[14], hy1 = wsm[15], hy2 = wsm[16],
                    hy3 = wsm[17], hy4 = wsm[18];
        const int ll = tid & 31;
        const int j2 = (tid >> 5) & 1;
        const int i2 = tid >> 6;
        const int rb = (4 * i2) * 10 + 4 * j2;
        const float hzw[5] = {hz0, hz1, hz2, hz3, hz4};
        float acc = 0.f;
        #pragma unroll
        for (int a = 0; a < 5; a++) {
            const int ra = rb + 10 * a;
            float ty = hy0 * xr2s[ra][ll]     + hy1 * xr2s[ra + 1][ll]
                     + hy2 * xr2s[ra + 2][ll] + hy3 * xr2s[ra + 3][ll]
                     + hy4 * xr2s[ra + 4][ll];
            acc += hzw[a] * ty;
        }
        const int od2 = (z0 >> 2) + i2;
        const int oh2 = (y0 >> 2) + j2;
        const int ow2 = (bxs >> 2) + ll;
        __stcs(out2 + ((size_t)od2 * 64 + oh2) * 64 + ow2, acc);
    }
}

extern "C" void kernel_launch(void* const* d_in, const int* in_sizes, int n_in,
                              void* d_out, int out_size)
{
    const float* x  = (const float*)d_in[0];
    const float* k0 = (const float*)d_in[1];
    const float* k1 = (const float*)d_in[2];
    float* out = (float*)d_out;

    dim3 grid(S / 128, S / 8, 32 * 2);   // (2, 32, 64) = 4096 blocks
    pyramid_kernel<<<grid, 320>>>(x, k0, k1, out);
}

// round 11
// speedup vs baseline: 1.0450x; 1.0450x over previous
#include <cuda_runtime.h>

// PyramidDownSampling fused: out = [ x copy (2x256^3) | d1 3^3 s2 (2x128^3) | d2 5^3 s4 (2x64^3) ]
// R10: warp-per-dz + depth-2 software-pipelined row loads (hide LDG latency).
//   Lane holds X[4l..4l+3] (float4). Copy = direct STG.128. x-conv via 2
//   shfl_up; lane0 patched from uniform left-halo float2.

#define S  256
#define SS 65536
#define FULLM 0xffffffffu

__global__ __launch_bounds__(320, 3)
void pyramid_kernel(const float* __restrict__ x,
                    const float* __restrict__ k0,   // 27  (3x3x3)
                    const float* __restrict__ k1,   // 125 (5x5x5)
                    float* __restrict__ out)
{
    __shared__ float xr1s[100][64];   // x-reduced for d1, rows r = dz*10+dy
    __shared__ float xr2s[100][32];   // x-reduced for d2
    __shared__ float wsm[24];         // gz[0:3) gy[3:6) gx[6:9) hz[9:14) hy[14:19) hx[19:24)

    const int tid  = threadIdx.x;
    const int w    = tid >> 5;        // 0..9 == dz
    const int lane = tid & 31;

    // ---- exact 1D factors = axis marginals of the 3D kernels ----
    if (tid < 24) {
        float s = 0.f;
        if (tid < 9) {
            int axis = tid / 3, idx = tid % 3;
            for (int u = 0; u < 3; u++)
                for (int v = 0; v < 3; v++) {
                    int a, b, c;
                    if (axis == 0) { a = idx; b = u; c = v; }
                    else if (axis == 1) { a = u; b = idx; c = v; }
                    else { a = u; b = v; c = idx; }
                    s += k0[(a * 3 + b) * 3 + c];
                }
        } else {
            int q = tid - 9, axis = q / 5, idx = q % 5;
            for (int u = 0; u < 5; u++)
                for (int v = 0; v < 5; v++) {
                    int a, b, c;
                    if (axis == 0) { a = idx; b = u; c = v; }
                    else if (axis == 1) { a = u; b = idx; c = v; }
                    else { a = u; b = v; c = idx; }
                    s += k1[(a * 5 + b) * 5 + c];
                }
        }
        wsm[tid] = s;
    }
    __syncthreads();

    const int bxs = blockIdx.x * 128;
    const int y0  = blockIdx.y * 8;
    const int zc  = blockIdx.z & 31;
    const int n   = blockIdx.z >> 5;
    const int z0  = zc * 8;

    const float* xn   = x   + (size_t)n * S * SS;
    float*       outx = out + (size_t)n * S * SS;
    float*       out1 = out + (size_t)2 * S * SS + (size_t)n * 2097152;
    float*       out2 = out + (size_t)2 * S * SS + (size_t)2 * 2097152
                            + (size_t)n * 262144;

    const float gxw0 = wsm[6],  gxw1 = wsm[7],  gxw2 = wsm[8];
    const float hxw0 = wsm[19], hxw1 = wsm[20], hxw2 = wsm[21],
                hxw3 = wsm[22], hxw4 = wsm[23];

    const int  gx    = bxs + 4 * lane;           // lane holds X[gx..gx+3]
    const bool bx0   = (bxs == 0);
    const int  hloff = bx0 ? 0 : bxs - 2;        // uniform left-halo float2

    // ---- Phase A: warp w == dz plane; dy rows, depth-2 pipelined loads ----
    {
        const int zs = z0 - 2 + w;               // <= 255 always
        const int gz = max(zs, 0);
        const float* zb = xn + ((size_t)gz << 16);
        float* ob = outx + ((size_t)zs << 16);   // used only when w >= 2
        const bool zint = (w >= 2);

        float4 vbuf[2];
        float2 hbuf[2];
        {   // preload dy = 0  (ys = y0-2 -> gy = max(...,0))
            const int gy0r = max(y0 - 2, 0);
            const float* rp = zb + (gy0r << 8);
            vbuf[0] = *(const float4*)(rp + gx);
            hbuf[0] = *(const float2*)(rp + hloff);
        }

        #pragma unroll
        for (int dy = 0; dy < 10; dy++) {
            // prefetch next row before touching current one
            if (dy < 9) {
                const int ysn = y0 - 1 + dy;             // (dy+1) row
                const int gyn = max(ysn, 0);
                const float* rpn = zb + (gyn << 8);
                vbuf[(dy + 1) & 1] = *(const float4*)(rpn + gx);
                hbuf[(dy + 1) & 1] = *(const float2*)(rpn + hloff);
            }

            const float4 v  = vbuf[dy & 1];
            const float2 hl = hbuf[dy & 1];
            const float  e0 = hl.x;                      // X[bxs-2] (clamped)
            const float  e1 = bx0 ? hl.x : hl.y;         // X[bxs-1] (clamped)
            const int    ys = y0 - 2 + dy;

            // identity copy straight from the load register
            if (zint && dy >= 2)
                __stcs((float4*)(ob + (ys << 8) + gx), v);

            // neighbor taps: X[4l-2], X[4l-1] = lane-1's v.z, v.w
            float p2 = __shfl_up_sync(FULLM, v.z, 1);
            float p3 = __shfl_up_sync(FULLM, v.w, 1);
            if (lane == 0) { p2 = e0; p3 = e1; }

            const int r = w * 10 + dy;
            float2 o1;
            o1.x = gxw0 * p3  + gxw1 * v.x + gxw2 * v.y;
            o1.y = gxw0 * v.y + gxw1 * v.z + gxw2 * v.w;
            *(float2*)&xr1s[r][2 * lane] = o1;

            xr2s[r][lane] = hxw0 * p2 + hxw1 * p3 + hxw2 * v.x
                          + hxw3 * v.y + hxw4 * v.z;
        }
    }
    __syncthreads();

    // ---- Phase B: d1 = 3x3 (z,y) taps -> 4i x 4j x 64l = 1024 outputs ----
    {
        const float gz0 = wsm[0], gz1 = wsm[1], gz2 = wsm[2];
        const float gy0 = wsm[3], gy1 = wsm[4], gy2 = wsm[5];
        for (int t = tid; t < 1024; t += 320) {
            const int l = t & 63;
            const int j = (t >> 6) & 3;
            const int i = t >> 8;
            const int rb = (2 * i + 1) * 10 + (2 * j + 1);
            float acc =
                gz0 * (gy0 * xr1s[rb     ][l] + gy1 * xr1s[rb +  1][l] + gy2 * xr1s[rb +  2][l])
              + gz1 * (gy0 * xr1s[rb + 10][l] + gy1 * xr1s[rb + 11][l] + gy2 * xr1s[rb + 12][l])
              + gz2 * (gy0 * xr1s[rb + 20][l] + gy1 * xr1s[rb + 21][l] + gy2 * xr1s[rb + 22][l]);
            const int od = (z0 >> 1) + i;
            const int oh = (y0 >> 1) + j;
            const int ow = (bxs >> 1) + l;
            __stcs(out1 + ((size_t)od * 128 + oh) * 128 + ow, acc);
        }
    }

    // ---- Phase B: d2 = 5x5 (z,y) taps -> 2i x 2j x 32l = 128 outputs ----
    if (tid < 128) {
        const float hz0 = wsm[9],  hz1 = wsm[10], hz2 = wsm[11],
                    hz3 = wsm[12], hz4 = wsm[13];
        const float hy0 = wsm[14], hy1 = wsm[15], hy2 = wsm[16],
                    hy3 = wsm[17], hy4 = wsm[18];
        const int ll = tid & 31;
        const int j2 = (tid >> 5) & 1;
        const int i2 = tid >> 6;
        const int rb = (4 * i2) * 10 + 4 * j2;
        const float hzw[5] = {hz0, hz1, hz2, hz3, hz4};
        float acc = 0.f;
        #pragma unroll
        for (int a = 0; a < 5; a++) {
            const int ra = rb + 10 * a;
            float ty = hy0 * xr2s[ra][ll]     + hy1 * xr2s[ra + 1][ll]
                     + hy2 * xr2s[ra + 2][ll] + hy3 * xr2s[ra + 3][ll]
                     + hy4 * xr2s[ra + 4][ll];
            acc += hzw[a] * ty;
        }
        const int od2 = (z0 >> 2) + i2;
        const int oh2 = (y0 >> 2) + j2;
        const int ow2 = (bxs >> 2) + ll;
        __stcs(out2 + ((size_t)od2 * 64 + oh2) * 64 + ow2, acc);
    }
}

extern "C" void kernel_launch(void* const* d_in, const int* in_sizes, int n_in,
                              void* d_out, int out_size)
{
    const float* x  = (const float*)d_in[0];
    const float* k0 = (const float*)d_in[1];
    const float* k1 = (const float*)d_in[2];
    float* out = (float*)d_out;

    dim3 grid(S / 128, S / 8, 32 * 2);   // (2, 32, 64) = 4096 blocks
    pyramid_kernel<<<grid, 320>>>(x, k0, k1, out);
}

// round 12
// speedup vs baseline: 1.1300x; 1.0814x over previous
#include <cuda_runtime.h>

// PyramidDownSampling fused: out = [ x copy (2x256^3) | d1 3^3 s2 (2x128^3) | d2 5^3 s4 (2x64^3) ]
// R12: TZ=16 tile (18 warps, warp-per-dz), dynamic smem, float4 Phase-B d1,
//      d2 on dedicated warps 16-17 (byte-balanced with d1 warps).

#define S  256
#define SS 65536
#define FULLM 0xffffffffu

#define XR1_ROWS 180            // 18 dz * 10 dy
#define DSMEM_FLOATS (180*64 + 180*32)

__global__ __launch_bounds__(576, 2)
void pyramid_kernel(const float* __restrict__ x,
                    const float* __restrict__ k0,   // 27  (3x3x3)
                    const float* __restrict__ k1,   // 125 (5x5x5)
                    float* __restrict__ out)
{
    extern __shared__ float dsm[];
    float (*xr1s)[64] = (float(*)[64])dsm;                    // 180 x 64
    float (*xr2s)[32] = (float(*)[32])(dsm + 180 * 64);       // 180 x 32
    __shared__ float wsm[24];   // gz[0:3) gy[3:6) gx[6:9) hz[9:14) hy[14:19) hx[19:24)

    const int tid  = threadIdx.x;
    const int w    = tid >> 5;        // 0..17 == dz
    const int lane = tid & 31;

    // ---- exact 1D factors = axis marginals of the 3D kernels ----
    if (tid < 24) {
        float s = 0.f;
        if (tid < 9) {
            int axis = tid / 3, idx = tid % 3;
            for (int u = 0; u < 3; u++)
                for (int v = 0; v < 3; v++) {
                    int a, b, c;
                    if (axis == 0) { a = idx; b = u; c = v; }
                    else if (axis == 1) { a = u; b = idx; c = v; }
                    else { a = u; b = v; c = idx; }
                    s += k0[(a * 3 + b) * 3 + c];
                }
        } else {
            int q = tid - 9, axis = q / 5, idx = q % 5;
            for (int u = 0; u < 5; u++)
                for (int v = 0; v < 5; v++) {
                    int a, b, c;
                    if (axis == 0) { a = idx; b = u; c = v; }
                    else if (axis == 1) { a = u; b = idx; c = v; }
                    else { a = u; b = v; c = idx; }
                    s += k1[(a * 5 + b) * 5 + c];
                }
        }
        wsm[tid] = s;
    }
    __syncthreads();

    const int bxs = blockIdx.x * 128;
    const int y0  = blockIdx.y * 8;
    const int zc  = blockIdx.z & 15;
    const int n   = blockIdx.z >> 4;
    const int z0  = zc * 16;

    const float* xn   = x   + (size_t)n * S * SS;
    float*       outx = out + (size_t)n * S * SS;
    float*       out1 = out + (size_t)2 * S * SS + (size_t)n * 2097152;
    float*       out2 = out + (size_t)2 * S * SS + (size_t)2 * 2097152
                            + (size_t)n * 262144;

    const float gxw0 = wsm[6],  gxw1 = wsm[7],  gxw2 = wsm[8];
    const float hxw0 = wsm[19], hxw1 = wsm[20], hxw2 = wsm[21],
                hxw3 = wsm[22], hxw4 = wsm[23];

    const int  gx    = bxs + 4 * lane;           // lane holds X[gx..gx+3]
    const bool bx0   = (bxs == 0);
    const int  hloff = bx0 ? 0 : bxs - 2;        // uniform left-halo float2

    // ---- Phase A: warp w == dz plane (18 planes); dy rows depth-2 pipelined ----
    {
        const int zs = z0 - 2 + w;               // <= 255 always
        const int gz = max(zs, 0);
        const float* zb = xn + ((size_t)gz << 16);
        float* ob = outx + ((size_t)zs << 16);   // used only when w >= 2
        const bool zint = (w >= 2);

        float4 vbuf[2];
        float2 hbuf[2];
        {   // preload dy = 0
            const int gy0r = max(y0 - 2, 0);
            const float* rp = zb + (gy0r << 8);
            vbuf[0] = *(const float4*)(rp + gx);
            hbuf[0] = *(const float2*)(rp + hloff);
        }

        #pragma unroll
        for (int dy = 0; dy < 10; dy++) {
            if (dy < 9) {
                const int ysn = y0 - 1 + dy;
                const int gyn = max(ysn, 0);
                const float* rpn = zb + (gyn << 8);
                vbuf[(dy + 1) & 1] = *(const float4*)(rpn + gx);
                hbuf[(dy + 1) & 1] = *(const float2*)(rpn + hloff);
            }

            const float4 v  = vbuf[dy & 1];
            const float2 hl = hbuf[dy & 1];
            const float  e0 = hl.x;
            const float  e1 = bx0 ? hl.x : hl.y;
            const int    ys = y0 - 2 + dy;

            if (zint && dy >= 2)
                __stcs((float4*)(ob + (ys << 8) + gx), v);

            float p2 = __shfl_up_sync(FULLM, v.z, 1);
            float p3 = __shfl_up_sync(FULLM, v.w, 1);
            if (lane == 0) { p2 = e0; p3 = e1; }

            const int r = w * 10 + dy;
            float2 o1;
            o1.x = gxw0 * p3  + gxw1 * v.x + gxw2 * v.y;
            o1.y = gxw0 * v.y + gxw1 * v.z + gxw2 * v.w;
            *(float2*)&xr1s[r][2 * lane] = o1;

            xr2s[r][lane] = hxw0 * p2 + hxw1 * p3 + hxw2 * v.x
                          + hxw3 * v.y + hxw4 * v.z;
        }
    }
    __syncthreads();

    // ---- Phase B: d1 (warps 0-15, float4) : 8i x 4j x 16l4 = 512 outputs ----
    if (tid < 512) {
        const float gz0 = wsm[0], gz1 = wsm[1], gz2 = wsm[2];
        const float gy0 = wsm[3], gy1 = wsm[4], gy2 = wsm[5];
        const int l4 = tid & 15;
        const int j  = (tid >> 4) & 3;
        const int i  = tid >> 6;                 // 0..7
        const int rb = (2 * i + 1) * 10 + (2 * j + 1);
        const int c0 = 4 * l4;

        float4 acc = make_float4(0.f, 0.f, 0.f, 0.f);
        const float gzw[3] = {gz0, gz1, gz2};
        #pragma unroll
        for (int a = 0; a < 3; a++) {
            const int ra = rb + 10 * a;
            const float4 r0 = *(const float4*)&xr1s[ra    ][c0];
            const float4 r1 = *(const float4*)&xr1s[ra + 1][c0];
            const float4 r2 = *(const float4*)&xr1s[ra + 2][c0];
            float4 ty;
            ty.x = gy0 * r0.x + gy1 * r1.x + gy2 * r2.x;
            ty.y = gy0 * r0.y + gy1 * r1.y + gy2 * r2.y;
            ty.z = gy0 * r0.z + gy1 * r1.z + gy2 * r2.z;
            ty.w = gy0 * r0.w + gy1 * r1.w + gy2 * r2.w;
            acc.x += gzw[a] * ty.x;
            acc.y += gzw[a] * ty.y;
            acc.z += gzw[a] * ty.z;
            acc.w += gzw[a] * ty.w;
        }
        const int od = (z0 >> 1) + i;
        const int oh = (y0 >> 1) + j;
        const int ow = (bxs >> 1) + c0;
        __stcs((float4*)(out1 + ((size_t)od * 128 + oh) * 128 + ow), acc);
    }
    // ---- Phase B: d2 (warps 16-17) : 4 outputs per thread = 256 total ----
    else {
        const float hz0 = wsm[9],  hz1 = wsm[10], hz2 = wsm[11],
                    hz3 = wsm[12], hz4 = wsm[13];
        const float hy0 = wsm[14], hy1 = wsm[15], hy2 = wsm[16],
                    hy3 = wsm[17], hy4 = wsm[18];
        const int t  = tid - 512;                // 0..63
        const int ll = t & 31;
        const int j2 = t >> 5;                   // 0..1
        const float hzw[5] = {hz0, hz1, hz2, hz3, hz4};
        #pragma unroll
        for (int i2 = 0; i2 < 4; i2++) {
            const int rb = (4 * i2) * 10 + 4 * j2;
            float acc = 0.f;
            #pragma unroll
            for (int a = 0; a < 5; a++) {
                const int ra = rb + 10 * a;
                float ty = hy0 * xr2s[ra][ll]     + hy1 * xr2s[ra + 1][ll]
                         + hy2 * xr2s[ra + 2][ll] + hy3 * xr2s[ra + 3][ll]
                         + hy4 * xr2s[ra + 4][ll];
                acc += hzw[a] * ty;
            }
            const int od2 = (z0 >> 2) + i2;
            const int oh2 = (y0 >> 2) + j2;
            const int ow2 = (bxs >> 2) + ll;
            __stcs(out2 + ((size_t)od2 * 64 + oh2) * 64 + ow2, acc);
        }
    }
}

extern "C" void kernel_launch(void* const* d_in, const int* in_sizes, int n_in,
                              void* d_out, int out_size)
{
    const float* x  = (const float*)d_in[0];
    const float* k0 = (const float*)d_in[1];
    const float* k1 = (const float*)d_in[2];
    float* out = (float*)d_out;

    const int smem_bytes = DSMEM_FLOATS * (int)sizeof(float);   // 69120
    cudaFuncSetAttribute(pyramid_kernel,
                         cudaFuncAttributeMaxDynamicSharedMemorySize, smem_bytes);

    dim3 grid(S / 128, S / 8, 16 * 2);   // (2, 32, 32) = 2048 blocks
    pyramid_kernel<<<grid, 576, smem_bytes>>>(x, k0, k1, out);
}

// round 15
// speedup vs baseline: 1.1824x; 1.0463x over previous
#include <cuda_runtime.h>

// PyramidDownSampling fused: out = [ x copy (2x256^3) | d1 3^3 s2 (2x128^3) | d2 5^3 s4 (2x64^3) ]
// R14 (= R13 re-run, spill-safe launch bounds): barrier-free warp-owned streaming.
//   Warp tile: x=128 (float4/lane), y=8 outputs (10 input rows), z=8 outputs
//   (10 slices). Per slice: batch-load 10 rows + halo, copy-store from regs,
//   x-conv via shfl, y-conv into per-slice accs, z-conv in rolling registers.
//   No data smem, no syncthreads in the stream loop.

#define S  256
#define SS 65536
#define FULLM 0xffffffffu

__global__ __launch_bounds__(128, 4)
void pyramid_kernel(const float* __restrict__ x,
                    const float* __restrict__ k0,   // 27  (3x3x3)
                    const float* __restrict__ k1,   // 125 (5x5x5)
                    float* __restrict__ out)
{
    __shared__ float wsm[24];   // gz[0:3) gy[3:6) gx[6:9) hz[9:14) hy[14:19) hx[19:24)

    const int tid  = threadIdx.x;
    const int w    = tid >> 5;        // 0..3 : y-strip within block
    const int lane = tid & 31;

    // ---- exact 1D factors = axis marginals of the 3D kernels ----
    if (tid < 24) {
        float s = 0.f;
        if (tid < 9) {
            int axis = tid / 3, idx = tid % 3;
            for (int u = 0; u < 3; u++)
                for (int v = 0; v < 3; v++) {
                    int a, b, c;
                    if (axis == 0) { a = idx; b = u; c = v; }
                    else if (axis == 1) { a = u; b = idx; c = v; }
                    else { a = u; b = v; c = idx; }
                    s += k0[(a * 3 + b) * 3 + c];
                }
        } else {
            int q = tid - 9, axis = q / 5, idx = q % 5;
            for (int u = 0; u < 5; u++)
                for (int v = 0; v < 5; v++) {
                    int a, b, c;
                    if (axis == 0) { a = idx; b = u; c = v; }
                    else if (axis == 1) { a = u; b = idx; c = v; }
                    else { a = u; b = v; c = idx; }
                    s += k1[(a * 5 + b) * 5 + c];
                }
        }
        wsm[tid] = s;
    }
    __syncthreads();

    const float gzw0 = wsm[0],  gzw1 = wsm[1],  gzw2 = wsm[2];
    const float gyw0 = wsm[3],  gyw1 = wsm[4],  gyw2 = wsm[5];
    const float gxw0 = wsm[6],  gxw1 = wsm[7],  gxw2 = wsm[8];
    const float hzw0 = wsm[9],  hzw1 = wsm[10], hzw2 = wsm[11],
                hzw3 = wsm[12], hzw4 = wsm[13];
    const float hyw0 = wsm[14], hyw1 = wsm[15], hyw2 = wsm[16],
                hyw3 = wsm[17], hyw4 = wsm[18];
    const float hxw0 = wsm[19], hxw1 = wsm[20], hxw2 = wsm[21],
                hxw3 = wsm[22], hxw4 = wsm[23];

    const int bxs = blockIdx.x * 128;
    const int y0  = (blockIdx.y * 4 + w) * 8;       // 0..248
    const int zc  = blockIdx.z & 31;
    const int n   = blockIdx.z >> 5;
    const int z0  = zc * 8;

    const float* xn   = x   + (size_t)n * S * SS;
    float*       outx = out + (size_t)n * S * SS;
    float*       out1 = out + (size_t)2 * S * SS + (size_t)n * 2097152;
    float*       out2 = out + (size_t)2 * S * SS + (size_t)2 * 2097152
                            + (size_t)n * 262144;

    const int  gx    = bxs + 4 * lane;              // lane holds X[gx..gx+3]
    const bool bx0   = (bxs == 0);
    const int  hloff = bx0 ? 0 : bxs - 2;           // left-halo float2 offset

    // rolling z accumulators
    float2 a1[4] = {{0.f,0.f},{0.f,0.f},{0.f,0.f},{0.f,0.f}};
    float  a2[2] = {0.f, 0.f};

    const int hy_row = max(y0 - 2 + (lane & 15), 0);  // for lane<10 halo load

    #pragma unroll
    for (int t = 0; t < 10; t++) {
        const int zs = z0 - 2 + t;                  // -2 .. 255
        const int gz = max(zs, 0);
        const float* zb = xn + ((size_t)gz << 16);

        // ---- batch loads: 10 row float4s + packed halo (lane<10) ----
        float4 v[10];
        #pragma unroll
        for (int dy = 0; dy < 10; dy++) {
            const int gy = max(y0 - 2 + dy, 0);
            v[dy] = *(const float4*)(zb + (gy << 8) + gx);
        }
        float2 hv = make_float2(0.f, 0.f);
        if (lane < 10)
            hv = *(const float2*)(zb + (hy_row << 8) + hloff);

        // ---- identity copy straight from load regs (interior z only) ----
        if (t >= 2) {
            float* ob = outx + ((size_t)zs << 16) + gx;
            #pragma unroll
            for (int dy = 2; dy < 10; dy++)
                __stcs((float4*)(ob + ((y0 - 2 + dy) << 8)), v[dy]);
        }

        // ---- x-conv per row + y accumulation ----
        float2 p1[4] = {{0.f,0.f},{0.f,0.f},{0.f,0.f},{0.f,0.f}};
        float  p2[2] = {0.f, 0.f};
        #pragma unroll
        for (int dy = 0; dy < 10; dy++) {
            const float4 vv = v[dy];
            float e0 = __shfl_sync(FULLM, hv.x, dy);
            float e1 = __shfl_sync(FULLM, hv.y, dy);
            float q2 = __shfl_up_sync(FULLM, vv.z, 1);   // X[4l-2]
            float q3 = __shfl_up_sync(FULLM, vv.w, 1);   // X[4l-1]
            if (lane == 0) { q2 = e0; q3 = bx0 ? e0 : e1; }

            if (dy >= 1) {   // d1 x-conv (rows 1..9 used)
                const float xr1x = gxw0 * q3  + gxw1 * vv.x + gxw2 * vv.y;
                const float xr1y = gxw0 * vv.y + gxw1 * vv.z + gxw2 * vv.w;
                #pragma unroll
                for (int j = 0; j < 4; j++) {
                    const int b = dy - (2 * j + 1);
                    if (b >= 0 && b < 3) {
                        const float gw = (b == 0) ? gyw0 : (b == 1) ? gyw1 : gyw2;
                        p1[j].x += gw * xr1x;
                        p1[j].y += gw * xr1y;
                    }
                }
            }
            if (dy <= 8) {   // d2 x-conv (rows 0..8 used)
                const float xr2 = hxw0 * q2 + hxw1 * q3 + hxw2 * vv.x
                                + hxw3 * vv.y + hxw4 * vv.z;
                #pragma unroll
                for (int j2 = 0; j2 < 2; j2++) {
                    const int b = dy - 4 * j2;
                    if (b >= 0 && b < 5) {
                        const float hw = (b == 0) ? hyw0 : (b == 1) ? hyw1 :
                                         (b == 2) ? hyw2 : (b == 3) ? hyw3 : hyw4;
                        p2[j2] += hw * xr2;
                    }
                }
            }
        }

        // ---- z rolling accumulation + stores ----
        if (t & 1) {                                  // zs odd
            if (t >= 3) {
                const int od = (zs - 1) >> 1;         // z0/2 + (t-3)/2
                float* o1p = out1 + ((size_t)od * 128 + (y0 >> 1)) * 128
                           + (bxs >> 1) + 2 * lane;
                #pragma unroll
                for (int j = 0; j < 4; j++) {
                    float2 ov = make_float2(a1[j].x + gzw2 * p1[j].x,
                                            a1[j].y + gzw2 * p1[j].y);
                    __stcs((float2*)(o1p + (size_t)j * 128), ov);
                }
            }
            #pragma unroll
            for (int j = 0; j < 4; j++) {
                a1[j].x = gzw0 * p1[j].x;
                a1[j].y = gzw0 * p1[j].y;
            }
        } else {
            #pragma unroll
            for (int j = 0; j < 4; j++) {
                a1[j].x += gzw1 * p1[j].x;
                a1[j].y += gzw1 * p1[j].y;
            }
        }

        if ((t & 3) == 0) {                           // zs ≡ 2 (mod 4)
            if (t >= 4) {
                const int od2 = (zs - 2) >> 2;        // z0/4 + (t-4)/4
                float* o2p = out2 + ((size_t)od2 * 64 + (y0 >> 2)) * 64
                           + (bxs >> 2) + lane;
                #pragma unroll
                for (int j2 = 0; j2 < 2; j2++)
                    __stcs(o2p + (size_t)j2 * 64, a2[j2] + hzw4 * p2[j2]);
            }
            #pragma unroll
            for (int j2 = 0; j2 < 2; j2++)
                a2[j2] = hzw0 * p2[j2];
        } else {
            const int ph = t & 3;
            const float hw = (ph == 1) ? hzw1 : (ph == 2) ? hzw2 : hzw3;
            #pragma unroll
            for (int j2 = 0; j2 < 2; j2++)
                a2[j2] += hw * p2[j2];
        }
    }
}

extern "C" void kernel_launch(void* const* d_in, const int* in_sizes, int n_in,
                              void* d_out, int out_size)
{
    const float* x  = (const float*)d_in[0];
    const float* k0 = (const float*)d_in[1];
    const float* k1 = (const float*)d_in[2];
    float* out = (float*)d_out;

    // warps: 2(x) * 32(y) * 32(zc) * 2(n) = 4096 ; blocks of 4 warps
    dim3 grid(2, 8, 32 * 2);    // (2, 8, 64) = 1024 blocks
    pyramid_kernel<<<grid, 128>>>(x, k0, k1, out);
}

// round 17
// speedup vs baseline: 1.2621x; 1.0674x over previous
#include <cuda_runtime.h>

// PyramidDownSampling fused: out = [ x copy (2x256^3) | d1 3^3 s2 (2x128^3) | d2 5^3 s4 (2x64^3) ]
// R16: barrier-free warp-owned streaming, z-tile 16 (single wave).
//   Warp tile: x=128 (float4/lane), y=8 outputs (10 input rows), z=16 outputs
//   (18 slices). Per slice: batch-load 10 rows + halo, copy-store from regs,
//   x-conv via shfl, y-conv into per-slice accs, z-conv in rolling registers.

#define S  256
#define SS 65536
#define FULLM 0xffffffffu

__global__ __launch_bounds__(128, 4)
void pyramid_kernel(const float* __restrict__ x,
                    const float* __restrict__ k0,   // 27  (3x3x3)
                    const float* __restrict__ k1,   // 125 (5x5x5)
                    float* __restrict__ out)
{
    __shared__ float wsm[24];   // gz[0:3) gy[3:6) gx[6:9) hz[9:14) hy[14:19) hx[19:24)

    const int tid  = threadIdx.x;
    const int w    = tid >> 5;        // 0..3 : y-strip within block
    const int lane = tid & 31;

    // ---- exact 1D factors = axis marginals of the 3D kernels ----
    if (tid < 24) {
        float s = 0.f;
        if (tid < 9) {
            int axis = tid / 3, idx = tid % 3;
            for (int u = 0; u < 3; u++)
                for (int v = 0; v < 3; v++) {
                    int a, b, c;
                    if (axis == 0) { a = idx; b = u; c = v; }
                    else if (axis == 1) { a = u; b = idx; c = v; }
                    else { a = u; b = v; c = idx; }
                    s += k0[(a * 3 + b) * 3 + c];
                }
        } else {
            int q = tid - 9, axis = q / 5, idx = q % 5;
            for (int u = 0; u < 5; u++)
                for (int v = 0; v < 5; v++) {
                    int a, b, c;
                    if (axis == 0) { a = idx; b = u; c = v; }
                    else if (axis == 1) { a = u; b = idx; c = v; }
                    else { a = u; b = v; c = idx; }
                    s += k1[(a * 5 + b) * 5 + c];
                }
        }
        wsm[tid] = s;
    }
    __syncthreads();

    const float gzw0 = wsm[0],  gzw1 = wsm[1],  gzw2 = wsm[2];
    const float gyw0 = wsm[3],  gyw1 = wsm[4],  gyw2 = wsm[5];
    const float gxw0 = wsm[6],  gxw1 = wsm[7],  gxw2 = wsm[8];
    const float hzw0 = wsm[9],  hzw1 = wsm[10], hzw2 = wsm[11],
                hzw3 = wsm[12], hzw4 = wsm[13];
    const float hyw0 = wsm[14], hyw1 = wsm[15], hyw2 = wsm[16],
                hyw3 = wsm[17], hyw4 = wsm[18];
    const float hxw0 = wsm[19], hxw1 = wsm[20], hxw2 = wsm[21],
                hxw3 = wsm[22], hxw4 = wsm[23];

    const int bxs = blockIdx.x * 128;
    const int y0  = (blockIdx.y * 4 + w) * 8;       // 0..248
    const int zc  = blockIdx.z & 15;
    const int n   = blockIdx.z >> 4;
    const int z0  = zc * 16;

    const float* xn   = x   + (size_t)n * S * SS;
    float*       outx = out + (size_t)n * S * SS;
    float*       out1 = out + (size_t)2 * S * SS + (size_t)n * 2097152;
    float*       out2 = out + (size_t)2 * S * SS + (size_t)2 * 2097152
                            + (size_t)n * 262144;

    const int  gx    = bxs + 4 * lane;              // lane holds X[gx..gx+3]
    const bool bx0   = (bxs == 0);
    const int  hloff = bx0 ? 0 : bxs - 2;           // left-halo float2 offset

    // rolling z accumulators
    float2 a1[4] = {{0.f,0.f},{0.f,0.f},{0.f,0.f},{0.f,0.f}};
    float  a2[2] = {0.f, 0.f};

    const int hy_row = max(y0 - 2 + (lane & 15), 0);  // for lane<10 halo load

    #pragma unroll 2
    for (int t = 0; t < 18; t++) {
        const int zs = z0 - 2 + t;                  // -2 .. 255
        const int gz = max(zs, 0);
        const float* zb = xn + ((size_t)gz << 16);

        // ---- batch loads: 10 row float4s + packed halo (lane<10) ----
        float4 v[10];
        #pragma unroll
        for (int dy = 0; dy < 10; dy++) {
            const int gy = max(y0 - 2 + dy, 0);
            v[dy] = *(const float4*)(zb + (gy << 8) + gx);
        }
        float2 hv = make_float2(0.f, 0.f);
        if (lane < 10)
            hv = *(const float2*)(zb + (hy_row << 8) + hloff);

        // ---- identity copy straight from load regs (interior z only) ----
        if (t >= 2) {
            float* ob = outx + ((size_t)zs << 16) + gx;
            #pragma unroll
            for (int dy = 2; dy < 10; dy++)
                __stcs((float4*)(ob + ((y0 - 2 + dy) << 8)), v[dy]);
        }

        // ---- x-conv per row + y accumulation ----
        float2 p1[4] = {{0.f,0.f},{0.f,0.f},{0.f,0.f},{0.f,0.f}};
        float  p2[2] = {0.f, 0.f};
        #pragma unroll
        for (int dy = 0; dy < 10; dy++) {
            const float4 vv = v[dy];
            float e0 = __shfl_sync(FULLM, hv.x, dy);
            float e1 = __shfl_sync(FULLM, hv.y, dy);
            float q2 = __shfl_up_sync(FULLM, vv.z, 1);   // X[4l-2]
            float q3 = __shfl_up_sync(FULLM, vv.w, 1);   // X[4l-1]
            if (lane == 0) { q2 = e0; q3 = bx0 ? e0 : e1; }

            if (dy >= 1) {   // d1 x-conv (rows 1..9 used)
                const float xr1x = gxw0 * q3  + gxw1 * vv.x + gxw2 * vv.y;
                const float xr1y = gxw0 * vv.y + gxw1 * vv.z + gxw2 * vv.w;
                #pragma unroll
                for (int j = 0; j < 4; j++) {
                    const int b = dy - (2 * j + 1);
                    if (b >= 0 && b < 3) {
                        const float gw = (b == 0) ? gyw0 : (b == 1) ? gyw1 : gyw2;
                        p1[j].x += gw * xr1x;
                        p1[j].y += gw * xr1y;
                    }
                }
            }
            if (dy <= 8) {   // d2 x-conv (rows 0..8 used)
                const float xr2 = hxw0 * q2 + hxw1 * q3 + hxw2 * vv.x
                                + hxw3 * vv.y + hxw4 * vv.z;
                #pragma unroll
                for (int j2 = 0; j2 < 2; j2++) {
                    const int b = dy - 4 * j2;
                    if (b >= 0 && b < 5) {
                        const float hw = (b == 0) ? hyw0 : (b == 1) ? hyw1 :
                                         (b == 2) ? hyw2 : (b == 3) ? hyw3 : hyw4;
                        p2[j2] += hw * xr2;
                    }
                }
            }
        }

        // ---- z rolling accumulation + stores ----
        if (t & 1) {                                  // zs odd
            if (t >= 3) {
                const int od = (zs - 1) >> 1;
                float* o1p = out1 + ((size_t)od * 128 + (y0 >> 1)) * 128
                           + (bxs >> 1) + 2 * lane;
                #pragma unroll
                for (int j = 0; j < 4; j++) {
                    float2 ov = make_float2(a1[j].x + gzw2 * p1[j].x,
                                            a1[j].y + gzw2 * p1[j].y);
                    __stcs((float2*)(o1p + (size_t)j * 128), ov);
                }
            }
            #pragma unroll
            for (int j = 0; j < 4; j++) {
                a1[j].x = gzw0 * p1[j].x;
                a1[j].y = gzw0 * p1[j].y;
            }
        } else {
            #pragma unroll
            for (int j = 0; j < 4; j++) {
                a1[j].x += gzw1 * p1[j].x;
                a1[j].y += gzw1 * p1[j].y;
            }
        }

        if ((t & 3) == 0) {                           // zs ≡ 2 (mod 4)
            if (t >= 4) {
                const int od2 = (zs - 2) >> 2;
                float* o2p = out2 + ((size_t)od2 * 64 + (y0 >> 2)) * 64
                           + (bxs >> 2) + lane;
                #pragma unroll
                for (int j2 = 0; j2 < 2; j2++)
                    __stcs(o2p + (size_t)j2 * 64, a2[j2] + hzw4 * p2[j2]);
            }
            #pragma unroll
            for (int j2 = 0; j2 < 2; j2++)
                a2[j2] = hzw0 * p2[j2];
        } else {
            const int ph = t & 3;
            const float hw = (ph == 1) ? hzw1 : (ph == 2) ? hzw2 : hzw3;
            #pragma unroll
            for (int j2 = 0; j2 < 2; j2++)
                a2[j2] += hw * p2[j2];
        }
    }
}

extern "C" void kernel_launch(void* const* d_in, const int* in_sizes, int n_in,
                              void* d_out, int out_size)
{
    const float* x  = (const float*)d_in[0];
    const float* k0 = (const float*)d_in[1];
    const float* k1 = (const float*)d_in[2];
    float* out = (float*)d_out;

    // warps: 2(x) * 32(y) * 16(zc) * 2(n) = 2048 ; blocks of 4 warps = 512
    dim3 grid(2, 8, 16 * 2);    // (2, 8, 32) = 512 blocks
    pyramid_kernel<<<grid, 128>>>(x, k0, k1, out);
}